// round 15
// baseline (speedup 1.0000x reference)
#include <cuda_runtime.h>
#include <cuda_bf16.h>
#include <cstdint>

// z: [32,256,32,32] f32; emb: [1024,256] f32
// out: [8388608 z_q_st][32768 idx-as-f32][1 loss] f32

#define CQ      256
#define HWQ     1024
#define NPX     32768
#define KQ      1024
#define ZQ_ELEMS 8388608
#define NUNITS  2048          // 512 tiles x 4 kb-blocks
#define NWORK   296           // 2 CTAs x 148 SMs, persistent

typedef unsigned long long u64;

// ---- device scratch (no allocations allowed) ----
__device__ float g_en2[KQ];
__device__ float g_zn2[NPX];
__device__ float g_bestv[NPX * 4];
__device__ int   g_besti[NPX * 4];
__device__ float g_part[512];
__device__ int   g_tdone[512];
__device__ int   g_unit;
__device__ int   g_done;

// ---------------------------------------------------------------------------
// Kernel 1: blocks 0-7 -> ||e_k||^2 (chain identical to passing kernel);
// blocks 8-263 -> ||z_n||^2, 2-way c-split (128 px/block, argmin-safe
// regrouping: zn2 perturbations shift distance rows uniformly).
// Also resets all counters.
// ---------------------------------------------------------------------------
__global__ void vq_pre(const float* __restrict__ emb, const float* __restrict__ z) {
    int t = threadIdx.x;
    if (blockIdx.x == 0) {
        if (t == 0) { g_unit = 0; g_done = 0; }
        g_tdone[t] = 0;
        g_tdone[256 + t] = 0;
    }
    if (blockIdx.x < 8) {
        int warp = (blockIdx.x * blockDim.x + t) >> 5;   // 0..63
        int lane = t & 31;
        for (int i = 0; i < 16; i++) {
            int k = warp * 16 + i;
            const float* row = emb + (long)k * CQ;
            float s = 0.0f;
            #pragma unroll
            for (int j = 0; j < 8; j++) {
                float v = row[lane + 32 * j];
                s = __fadd_rn(s, __fmul_rn(v, v));
            }
            #pragma unroll
            for (int off = 16; off; off >>= 1)
                s = __fadd_rn(s, __shfl_xor_sync(0xffffffffu, s, off));
            if (lane == 0) g_en2[k] = s;
        }
    } else {
        __shared__ float sh[256];
        int pxl = t & 127, half = t >> 7;
        int n = (blockIdx.x - 8) * 128 + pxl;
        int bb = n >> 10, hw = n & 1023;
        const float* p = z + ((long)bb << 18) + hw + ((long)(half * 128) << 10);
        float acc = 0.0f;
        #pragma unroll 16
        for (int c = 0; c < 128; c++) {
            float v = p[(long)c << 10];
            acc = fmaf(v, v, acc);
        }
        sh[t] = acc;
        __syncthreads();
        if (half == 0) g_zn2[n] = __fadd_rn(sh[t], sh[t + 128]);
    }
}

// ---------------------------------------------------------------------------
// Kernel 2: persistent unit-stealing distance-GEMM + per-unit argmin +
// inline per-tile gather/STE/loss on tile completion (overlaps GEMM tail).
// GEMM chains, fold rounding, code order and tie rules bit-identical to
// the 361us passing kernel.
// ---------------------------------------------------------------------------
#define ZS0 0
#define ZS1 2048
#define ES0 4096
#define ESB 9216          // 256 * 36
#define SMEM_FLOATS 22528
#define SMEM_BYTES (SMEM_FLOATS * 4)   // 90112
#define GSTR 259

__device__ __forceinline__ void cpasync16(uint32_t dst, const void* src) {
    asm volatile("cp.async.cg.shared.global [%0], [%1], 16;" :: "r"(dst), "l"(src));
}

__device__ __forceinline__ void fill_stage(uint32_t sm32, const float* zbase,
                                           const float* emb, int kb, int cb,
                                           int b, int t) {
    #pragma unroll
    for (int i = 0; i < 2; i++) {
        int idx = t + (i << 8);
        int cl = idx >> 4;
        int q  = (idx & 15) << 2;
        const float* src = zbase + (long)(cb + cl) * HWQ + q;
        uint32_t dst = sm32 + (uint32_t)(((b ? ZS1 : ZS0) + cl * 64 + q) << 2);
        cpasync16(dst, src);
    }
    #pragma unroll
    for (int i = 0; i < 8; i++) {
        int idx = t + (i << 8);
        int k = idx >> 3;
        int q = (idx & 7) << 2;
        const float* src = emb + (long)(kb + k) * CQ + cb + q;
        uint32_t dst = sm32 + (uint32_t)((ES0 + b * ESB + k * 36 + q) << 2);
        cpasync16(dst, src);
    }
}

__device__ __forceinline__ void compute_stage(const float* __restrict__ zsp,
                                              const float* __restrict__ ep0,
                                              int pxA, int pxB, u64 acc[4][8]) {
    #pragma unroll 4
    for (int c = 0; c < 32; c++) {
        const float* zr = zsp + c * 64;
        ulonglong2 za = *(const ulonglong2*)(zr + pxA);
        ulonglong2 zb = *(const ulonglong2*)(zr + pxB);
        float ef[8];
        #pragma unroll
        for (int j = 0; j < 8; j++) ef[j] = ep0[j * (32 * 36) + c];
        #pragma unroll
        for (int j = 0; j < 8; j++) {
            u64 ed;
            asm("mov.b64 %0, {%1, %1};" : "=l"(ed) : "f"(ef[j]));
            asm("fma.rn.f32x2 %0, %1, %2, %0;" : "+l"(acc[0][j]) : "l"(za.x), "l"(ed));
            asm("fma.rn.f32x2 %0, %1, %2, %0;" : "+l"(acc[1][j]) : "l"(za.y), "l"(ed));
            asm("fma.rn.f32x2 %0, %1, %2, %0;" : "+l"(acc[2][j]) : "l"(zb.x), "l"(ed));
            asm("fma.rn.f32x2 %0, %1, %2, %0;" : "+l"(acc[3][j]) : "l"(zb.y), "l"(ed));
        }
    }
}

__global__ void __launch_bounds__(256, 2)
vq_unit(const float* __restrict__ z, const float* __restrict__ emb,
        float* __restrict__ outz, float* __restrict__ out_idx,
        float* __restrict__ out_all) {
    extern __shared__ float smem[];
    uint32_t sm32 = (uint32_t)__cvta_generic_to_shared(smem);
    __shared__ int s_u, s_fin, s_last;
    __shared__ int idxs[64];
    __shared__ float ws[8];
    __shared__ double red[256];

    const int t  = threadIdx.x;
    const int pg = t & 7;
    const int kg = t >> 3;
    const int pxA = pg * 4;
    const int pxB = 32 + pg * 4;

    float* redv = smem;                    // [32][64]  (reused post-compute)
    int*   redi = (int*)(smem + 2048);

    while (true) {
        __syncthreads();
        if (t == 0) s_u = atomicAdd(&g_unit, 1);
        __syncthreads();
        int u = s_u;
        if (u >= NUNITS) break;

        const int tile = u >> 2;
        const int kb   = (u & 3) << 8;
        const int bb   = tile >> 4;
        const int hw0  = (tile & 15) << 6;
        const float* zbase = z + ((long)bb << 18) + hw0;

        float zn2p[8];
        #pragma unroll
        for (int j = 0; j < 8; j++) {
            int px = (j < 4) ? (pxA + j) : (pxB + j - 4);
            zn2p[j] = g_zn2[tile * 64 + px];
        }

        u64 acc[4][8];
        #pragma unroll
        for (int pp = 0; pp < 4; pp++)
            #pragma unroll
            for (int j = 0; j < 8; j++) acc[pp][j] = 0ull;

        fill_stage(sm32, zbase, emb, kb, 0, 0, t);
        asm volatile("cp.async.commit_group;" ::: "memory");

        for (int s = 0; s < 8; s++) {
            asm volatile("cp.async.wait_group 0;" ::: "memory");
            __syncthreads();
            if (s < 7) {
                fill_stage(sm32, zbase, emb, kb, (s + 1) << 5, (s + 1) & 1, t);
                asm volatile("cp.async.commit_group;" ::: "memory");
            }
            const int b = s & 1;
            compute_stage(smem + (b ? ZS1 : ZS0), smem + ES0 + b * ESB + kg * 36,
                          pxA, pxB, acc);
        }

        // fold: d = fl( fl(zn2+en2) - fl(2*dot) ); codes kb+kg+32j ascending
        float bestv[8];
        int   besti[8];
        #pragma unroll
        for (int i = 0; i < 8; i++) { bestv[i] = 3.402823466e38f; besti[i] = 0x7fffffff; }
        #pragma unroll
        for (int j = 0; j < 8; j++) {
            int code = kb + kg + 32 * j;
            float e2 = g_en2[code];
            #pragma unroll
            for (int pp = 0; pp < 4; pp++) {
                float lo, hi;
                asm("mov.b64 {%0, %1}, %2;" : "=f"(lo), "=f"(hi) : "l"(acc[pp][j]));
                int i2 = pp * 2;
                float s0 = __fadd_rn(zn2p[i2],     e2);
                float s1 = __fadd_rn(zn2p[i2 + 1], e2);
                float v0 = __fadd_rn(s0, __fmul_rn(-2.0f, lo));
                float v1 = __fadd_rn(s1, __fmul_rn(-2.0f, hi));
                if (v0 < bestv[i2])     { bestv[i2]     = v0; besti[i2]     = code; }
                if (v1 < bestv[i2 + 1]) { bestv[i2 + 1] = v1; besti[i2 + 1] = code; }
            }
        }

        // cross-kg reduction; tie -> lowest index
        __syncthreads();
        #pragma unroll
        for (int j = 0; j < 8; j++) {
            int px = (j < 4) ? (pxA + j) : (pxB + j - 4);
            redv[kg * 64 + px] = bestv[j];
            redi[kg * 64 + px] = besti[j];
        }
        __syncthreads();
        if (t < 64) {
            float bv = redv[t];
            int   bi = redi[t];
            #pragma unroll 4
            for (int g = 1; g < 32; g++) {
                float v = redv[g * 64 + t];
                int   i = redi[g * 64 + t];
                if (v < bv || (v == bv && i < bi)) { bv = v; bi = i; }
            }
            int n = tile * 64 + t;
            g_bestv[n * 4 + (u & 3)] = bv;
            g_besti[n * 4 + (u & 3)] = bi;
        }

        // ---- tile completion: last unit of the tile does gather/STE/loss
        __syncthreads();
        if (t == 0) {
            __threadfence();
            s_fin = (atomicAdd(&g_tdone[tile], 1) == 3);
        }
        __syncthreads();
        if (s_fin) {
            __threadfence();
            // merge 4 kb-blocks (ascending kb, strict < => lowest index on ties)
            if (t < 64) {
                int n = tile * 64 + t;
                float bv = g_bestv[n * 4];
                int   bi = g_besti[n * 4];
                #pragma unroll
                for (int s = 1; s < 4; s++) {
                    float v = g_bestv[n * 4 + s];
                    int   i = g_besti[n * 4 + s];
                    if (v < bv) { bv = v; bi = i; }
                }
                idxs[t] = bi;
                out_idx[n] = (float)bi;
            }
            __syncthreads();
            {   // stage 64 emb rows into smem [64][GSTR]
                int r = t >> 2, part = t & 3;
                const float4* er = (const float4*)(emb + (long)idxs[r] * CQ);
                float* d = smem + r * GSTR;
                #pragma unroll
                for (int i = 0; i < 16; i++) {
                    float4 v = er[part + i * 4];
                    int c = (part + i * 4) * 4;
                    d[c] = v.x; d[c + 1] = v.y; d[c + 2] = v.z; d[c + 3] = v.w;
                }
            }
            __syncthreads();
            int px = t & 63, c0 = t >> 6;
            float* ob = outz + ((long)bb << 18) + hw0;
            float accl = 0.0f;
            #pragma unroll 4
            for (int i = 0; i < 64; i++) {
                int c = i * 4 + c0;
                float zv = zbase[(long)c * HWQ + px];
                float qv = smem[px * GSTR + c];
                float d0 = __fadd_rn(qv, -zv);
                ob[(long)c * HWQ + px] = __fadd_rn(zv, d0);   // == z + sg(z_q - z)
                accl = fmaf(d0, d0, accl);
            }
            #pragma unroll
            for (int off = 16; off; off >>= 1)
                accl += __shfl_xor_sync(0xffffffffu, accl, off);
            if ((t & 31) == 0) ws[t >> 5] = accl;
            __syncthreads();
            if (t == 0) {
                float tot = 0.0f;
                #pragma unroll
                for (int i = 0; i < 8; i++) tot += ws[i];
                g_part[tile] = tot;
                __threadfence();
                s_last = (atomicAdd(&g_done, 1) == 511);
            }
            __syncthreads();
            if (s_last) {                       // final deterministic loss
                __threadfence();
                double sd = 0.0;
                for (int i = t; i < 512; i += 256) sd += (double)g_part[i];
                red[t] = sd;
                __syncthreads();
                for (int st = 128; st; st >>= 1) {
                    if (t < st) red[t] += red[t + st];
                    __syncthreads();
                }
                if (t == 0) {
                    float m = (float)(red[0] / 8388608.0);
                    out_all[ZQ_ELEMS + NPX] = 0.25f * m + m;
                }
            }
        }
    }
}

// ---------------------------------------------------------------------------
extern "C" void kernel_launch(void* const* d_in, const int* in_sizes, int n_in,
                              void* d_out, int out_size) {
    const float* z   = (const float*)d_in[0];
    const float* emb = (const float*)d_in[1];
    float* out = (float*)d_out;

    cudaFuncSetAttribute(vq_unit, cudaFuncAttributeMaxDynamicSharedMemorySize,
                         SMEM_BYTES);

    vq_pre<<<264, 256>>>(emb, z);
    vq_unit<<<NWORK, 256, SMEM_BYTES>>>(z, emb, out, out + ZQ_ELEMS, out);
}

// round 16
// speedup vs baseline: 1.1087x; 1.1087x over previous
#include <cuda_runtime.h>
#include <cuda_bf16.h>
#include <cstdint>

// z: [32,256,32,32] f32; emb: [1024,256] f32
// out: [8388608 z_q_st][32768 idx-as-f32][1 loss] f32

#define CQ      256
#define HWQ     1024
#define NPX     32768
#define KQ      1024
#define ZQ_ELEMS 8388608
#define NUNITS  2048          // 512 tiles x 4 kb-blocks
#define NWORK   296           // 2 CTAs x 148 SMs, persistent

typedef unsigned long long u64;

// ---- device scratch (no allocations allowed) ----
__device__ float g_en2[KQ];
__device__ float g_zn2[NPX];
__device__ float g_bestv[NPX * 4];
__device__ int   g_besti[NPX * 4];
__device__ float g_part[1024];
__device__ int   g_unit;
__device__ int   g_done;

// ---------------------------------------------------------------------------
// Kernel 1: blocks 0-7 -> ||e_k||^2 (chain identical to passing kernel);
// blocks 8-263 -> ||z_n||^2 with 2-way c-split (verified rel_err=0.0 in R14;
// zn2 regrouping shifts each pixel's distance row uniformly -> argmin-safe).
// Also resets counters.
// ---------------------------------------------------------------------------
__global__ void vq_pre(const float* __restrict__ emb, const float* __restrict__ z) {
    int t = threadIdx.x;
    if (blockIdx.x == 0 && t == 0) { g_unit = 0; g_done = 0; }
    if (blockIdx.x < 8) {
        int warp = (blockIdx.x * blockDim.x + t) >> 5;   // 0..63
        int lane = t & 31;
        for (int i = 0; i < 16; i++) {
            int k = warp * 16 + i;
            const float* row = emb + (long)k * CQ;
            float s = 0.0f;
            #pragma unroll
            for (int j = 0; j < 8; j++) {
                float v = row[lane + 32 * j];
                s = __fadd_rn(s, __fmul_rn(v, v));
            }
            #pragma unroll
            for (int off = 16; off; off >>= 1)
                s = __fadd_rn(s, __shfl_xor_sync(0xffffffffu, s, off));
            if (lane == 0) g_en2[k] = s;
        }
    } else {
        __shared__ float sh[256];
        int pxl = t & 127, half = t >> 7;
        int n = (blockIdx.x - 8) * 128 + pxl;
        int bb = n >> 10, hw = n & 1023;
        const float* p = z + ((long)bb << 18) + hw + ((long)(half * 128) << 10);
        float acc = 0.0f;
        #pragma unroll 16
        for (int c = 0; c < 128; c++) {
            float v = p[(long)c << 10];
            acc = fmaf(v, v, acc);
        }
        sh[t] = acc;
        __syncthreads();
        if (half == 0) g_zn2[n] = __fadd_rn(sh[t], sh[t + 128]);
    }
}

// ---------------------------------------------------------------------------
// Kernel 2: persistent unit-stealing distance-GEMM + per-unit argmin.
// BYTE-IDENTICAL to the 361us R13 version (at the FFMA2 RF-banking floor;
// R14 proved that fusing tail work here costs ~60us of GEMM throughput).
// ---------------------------------------------------------------------------
#define ZS0 0
#define ZS1 2048
#define ES0 4096
#define ESB 9216          // 256 * 36
#define SMEM_FLOATS 22528
#define SMEM_BYTES (SMEM_FLOATS * 4)   // 90112

__device__ __forceinline__ void cpasync16(uint32_t dst, const void* src) {
    asm volatile("cp.async.cg.shared.global [%0], [%1], 16;" :: "r"(dst), "l"(src));
}

__device__ __forceinline__ void fill_stage(uint32_t sm32, const float* zbase,
                                           const float* emb, int kb, int cb,
                                           int b, int t) {
    #pragma unroll
    for (int i = 0; i < 2; i++) {
        int idx = t + (i << 8);
        int cl = idx >> 4;
        int q  = (idx & 15) << 2;
        const float* src = zbase + (long)(cb + cl) * HWQ + q;
        uint32_t dst = sm32 + (uint32_t)(((b ? ZS1 : ZS0) + cl * 64 + q) << 2);
        cpasync16(dst, src);
    }
    #pragma unroll
    for (int i = 0; i < 8; i++) {
        int idx = t + (i << 8);
        int k = idx >> 3;
        int q = (idx & 7) << 2;
        const float* src = emb + (long)(kb + k) * CQ + cb + q;
        uint32_t dst = sm32 + (uint32_t)((ES0 + b * ESB + k * 36 + q) << 2);
        cpasync16(dst, src);
    }
}

__device__ __forceinline__ void compute_stage(const float* __restrict__ zsp,
                                              const float* __restrict__ ep0,
                                              int pxA, int pxB, u64 acc[4][8]) {
    #pragma unroll 4
    for (int c = 0; c < 32; c++) {
        const float* zr = zsp + c * 64;
        ulonglong2 za = *(const ulonglong2*)(zr + pxA);
        ulonglong2 zb = *(const ulonglong2*)(zr + pxB);
        float ef[8];
        #pragma unroll
        for (int j = 0; j < 8; j++) ef[j] = ep0[j * (32 * 36) + c];
        #pragma unroll
        for (int j = 0; j < 8; j++) {
            u64 ed;
            asm("mov.b64 %0, {%1, %1};" : "=l"(ed) : "f"(ef[j]));
            asm("fma.rn.f32x2 %0, %1, %2, %0;" : "+l"(acc[0][j]) : "l"(za.x), "l"(ed));
            asm("fma.rn.f32x2 %0, %1, %2, %0;" : "+l"(acc[1][j]) : "l"(za.y), "l"(ed));
            asm("fma.rn.f32x2 %0, %1, %2, %0;" : "+l"(acc[2][j]) : "l"(zb.x), "l"(ed));
            asm("fma.rn.f32x2 %0, %1, %2, %0;" : "+l"(acc[3][j]) : "l"(zb.y), "l"(ed));
        }
    }
}

__global__ void __launch_bounds__(256, 2)
vq_unit(const float* __restrict__ z, const float* __restrict__ emb) {
    extern __shared__ float smem[];
    uint32_t sm32 = (uint32_t)__cvta_generic_to_shared(smem);
    __shared__ int s_u;

    const int t  = threadIdx.x;
    const int pg = t & 7;
    const int kg = t >> 3;
    const int pxA = pg * 4;
    const int pxB = 32 + pg * 4;

    float* redv = smem;                    // [32][64]  (reused post-compute)
    int*   redi = (int*)(smem + 2048);

    while (true) {
        __syncthreads();
        if (t == 0) s_u = atomicAdd(&g_unit, 1);
        __syncthreads();
        int u = s_u;
        if (u >= NUNITS) break;

        const int tile = u >> 2;
        const int kb   = (u & 3) << 8;
        const int bb   = tile >> 4;
        const int hw0  = (tile & 15) << 6;
        const float* zbase = z + ((long)bb << 18) + hw0;

        float zn2p[8];
        #pragma unroll
        for (int j = 0; j < 8; j++) {
            int px = (j < 4) ? (pxA + j) : (pxB + j - 4);
            zn2p[j] = g_zn2[tile * 64 + px];
        }

        u64 acc[4][8];
        #pragma unroll
        for (int pp = 0; pp < 4; pp++)
            #pragma unroll
            for (int j = 0; j < 8; j++) acc[pp][j] = 0ull;

        fill_stage(sm32, zbase, emb, kb, 0, 0, t);
        asm volatile("cp.async.commit_group;" ::: "memory");

        for (int s = 0; s < 8; s++) {
            asm volatile("cp.async.wait_group 0;" ::: "memory");
            __syncthreads();
            if (s < 7) {
                fill_stage(sm32, zbase, emb, kb, (s + 1) << 5, (s + 1) & 1, t);
                asm volatile("cp.async.commit_group;" ::: "memory");
            }
            const int b = s & 1;
            compute_stage(smem + (b ? ZS1 : ZS0), smem + ES0 + b * ESB + kg * 36,
                          pxA, pxB, acc);
        }

        // fold: d = fl( fl(zn2+en2) - fl(2*dot) ); codes kb+kg+32j ascending
        float bestv[8];
        int   besti[8];
        #pragma unroll
        for (int i = 0; i < 8; i++) { bestv[i] = 3.402823466e38f; besti[i] = 0x7fffffff; }
        #pragma unroll
        for (int j = 0; j < 8; j++) {
            int code = kb + kg + 32 * j;
            float e2 = g_en2[code];
            #pragma unroll
            for (int pp = 0; pp < 4; pp++) {
                float lo, hi;
                asm("mov.b64 {%0, %1}, %2;" : "=f"(lo), "=f"(hi) : "l"(acc[pp][j]));
                int i2 = pp * 2;
                float s0 = __fadd_rn(zn2p[i2],     e2);
                float s1 = __fadd_rn(zn2p[i2 + 1], e2);
                float v0 = __fadd_rn(s0, __fmul_rn(-2.0f, lo));
                float v1 = __fadd_rn(s1, __fmul_rn(-2.0f, hi));
                if (v0 < bestv[i2])     { bestv[i2]     = v0; besti[i2]     = code; }
                if (v1 < bestv[i2 + 1]) { bestv[i2 + 1] = v1; besti[i2 + 1] = code; }
            }
        }

        __syncthreads();
        #pragma unroll
        for (int j = 0; j < 8; j++) {
            int px = (j < 4) ? (pxA + j) : (pxB + j - 4);
            redv[kg * 64 + px] = bestv[j];
            redi[kg * 64 + px] = besti[j];
        }
        __syncthreads();
        if (t < 64) {
            float bv = redv[t];
            int   bi = redi[t];
            #pragma unroll 4
            for (int g = 1; g < 32; g++) {
                float v = redv[g * 64 + t];
                int   i = redi[g * 64 + t];
                if (v < bv || (v == bv && i < bi)) { bv = v; bi = i; }
            }
            int n = tile * 64 + t;
            g_bestv[n * 4 + (u & 3)] = bv;
            g_besti[n * 4 + (u & 3)] = bi;
        }
    }
}

// ---------------------------------------------------------------------------
// Kernel 3: cross-kb final argmin + gather + STE + loss partials + fused
// last-block final loss reduction (R13 version — in the 361us run).
// ---------------------------------------------------------------------------
#define GSTR 259
__global__ __launch_bounds__(256) void vq_gather(const float* __restrict__ z,
                                                 const float* __restrict__ emb,
                                                 float* __restrict__ outz,
                                                 float* __restrict__ out_idx,
                                                 float* __restrict__ out_all) {
    extern __shared__ float srows[];           // [32][GSTR]
    __shared__ int idxs[32];
    __shared__ float ws[8];
    __shared__ int lastflag;
    int t = threadIdx.x, blk = blockIdx.x;
    int bb = blk >> 5, hw0 = (blk & 31) << 5;

    if (t < 32) {
        int n = blk * 32 + t;                  // == bb*HWQ + hw0 + t
        float bv = g_bestv[n * 4];
        int   bi = g_besti[n * 4];
        #pragma unroll
        for (int s = 1; s < 4; s++) {          // ascending kb, strict < => lowest idx
            float v = g_bestv[n * 4 + s];
            int   i = g_besti[n * 4 + s];
            if (v < bv) { bv = v; bi = i; }
        }
        idxs[t] = bi;
        out_idx[n] = (float)bi;
    }
    __syncthreads();
    {   // stage 32 emb rows; interleaved float4 layout -> 32 distinct banks
        int r = t >> 3, part = t & 7;
        const float4* er = (const float4*)(emb + (long)idxs[r] * CQ);
        float* d = srows + r * GSTR;
        #pragma unroll
        for (int i = 0; i < 8; i++) {
            float4 v = er[part + i * 8];
            int c = (part + i * 8) * 4;
            d[c] = v.x; d[c + 1] = v.y; d[c + 2] = v.z; d[c + 3] = v.w;
        }
    }
    __syncthreads();
    int px = t & 31, c0 = t >> 5;              // 8 c-groups
    const float* zb = z + ((long)bb << 18) + hw0;
    float* ob = outz + ((long)bb << 18) + hw0;
    float acc = 0.0f;
    #pragma unroll 8
    for (int i = 0; i < 32; i++) {
        int c = i * 8 + c0;
        float zv = zb[(long)c * HWQ + px];
        float qv = srows[px * GSTR + c];
        float d0 = __fadd_rn(qv, -zv);
        ob[(long)c * HWQ + px] = __fadd_rn(zv, d0);     // == z + sg(z_q - z)
        acc = fmaf(d0, d0, acc);
    }
    #pragma unroll
    for (int off = 16; off; off >>= 1)
        acc += __shfl_xor_sync(0xffffffffu, acc, off);
    if ((t & 31) == 0) ws[t >> 5] = acc;
    __syncthreads();
    if (t == 0) {
        float tot = 0.0f;
        #pragma unroll
        for (int i = 0; i < 8; i++) tot += ws[i];
        g_part[blk] = tot;
        __threadfence();
        lastflag = (atomicAdd(&g_done, 1) == 1023);
    }
    __syncthreads();
    if (lastflag) {                            // final deterministic loss
        __shared__ double red[256];
        double s = 0.0;
        for (int i = t; i < 1024; i += 256) s += (double)g_part[i];
        red[t] = s;
        __syncthreads();
        for (int st = 128; st; st >>= 1) {
            if (t < st) red[t] += red[t + st];
            __syncthreads();
        }
        if (t == 0) {
            float m = (float)(red[0] / 8388608.0);
            out_all[ZQ_ELEMS + NPX] = 0.25f * m + m;
        }
    }
}

// ---------------------------------------------------------------------------
extern "C" void kernel_launch(void* const* d_in, const int* in_sizes, int n_in,
                              void* d_out, int out_size) {
    const float* z   = (const float*)d_in[0];
    const float* emb = (const float*)d_in[1];
    float* out = (float*)d_out;

    cudaFuncSetAttribute(vq_unit, cudaFuncAttributeMaxDynamicSharedMemorySize,
                         SMEM_BYTES);
    cudaFuncSetAttribute(vq_gather, cudaFuncAttributeMaxDynamicSharedMemorySize,
                         32 * GSTR * 4);

    vq_pre<<<264, 256>>>(emb, z);
    vq_unit<<<NWORK, 256, SMEM_BYTES>>>(z, emb);
    vq_gather<<<1024, 256, 32 * GSTR * 4>>>(z, emb, out, out + ZQ_ELEMS, out);
}